// round 8
// baseline (speedup 1.0000x reference)
#include <cuda_runtime.h>

// ---------------------------------------------------------------------------
// MultiLevelClassifier — routed experts, round 5.
//
// R4 post-mortem: fin kernels + launch bubbles dominate (ncu shows only one
// launch; the visible gemm is ~15% of total). This round fuses the
// finish stage (split-K reduce -> LN -> ReLU -> W2 -> argmax -> scatter)
// into the gemm kernel via the last-block-reduces pattern:
//   each (expert,chunk) has a global ticket; after writing partials each of
//   the FSEG seg-blocks increments it; the 8th arriver resets the ticket
//   (self-reset -> zero-init invariant holds across graph replays) and runs
//   the finish for that chunk. 7 launches -> 4.
// Gemm: RT rows x 4 cols register tile, weights via LDG.128 (unroll 8 for
// ~8 loads in flight/thread), features duplicated in smem so one LDS.64
// yields the f32x2 multiplicand.
// ---------------------------------------------------------------------------

#define BB   1024
#define FF   1024
#define EE   256
#define L1C  16
#define L2C  8
#define L3C  32
#define NE3  128
#define FSEG 8
#define FS   (FF / FSEG)   // 128

// scratch (device globals — no allocation allowed; zero-initialized)
__device__ int   g_cnt2[L1C];
__device__ int   g_cnt3[NE3];
__device__ int   g_rows2[L1C * BB];
__device__ int   g_rows3[NE3 * BB];
__device__ float g_part[FSEG * BB * EE];   // 8 MB split-K partials
__device__ int   g_tick1[64];              // BB/16 chunks
__device__ int   g_tick2[L1C * 64];        // 16 experts x (BB/16)
__device__ int   g_tick3[NE3 * 128];       // 128 experts x (BB/8)

// ---- packed f32x2 helpers --------------------------------------------------
__device__ __forceinline__ void fma_f32x2(unsigned long long& d,
                                          unsigned long long a,
                                          unsigned long long b) {
    asm("fma.rn.f32x2 %0, %1, %2, %0;" : "+l"(d) : "l"(a), "l"(b));
}
__device__ __forceinline__ float2 unpack2(unsigned long long v) {
    float2 r;
    asm("mov.b64 {%0, %1}, %2;" : "=f"(r.x), "=f"(r.y) : "l"(v));
    return r;
}

// ---------------------------------------------------------------------------
__global__ void k_init() {
    int t = threadIdx.x;
    if (t < L1C) g_cnt2[t] = 0;
    if (t < NE3) g_cnt3[t] = 0;
}

// ---------------------------------------------------------------------------
// Fused level kernel. Block (slot, seg, expert), 256 threads.
// GEMM: cg = tid&63 -> cols 4cg..4cg+3 (LDG.128 weights), rg = tid>>6 ->
// rows rg*RT..  (R = 4*RT rows/chunk). Finish runs in the last seg-block.
// ---------------------------------------------------------------------------
template <int RT, int L, bool MIX, bool DENSE>
__global__ __launch_bounds__(256) void k_level(
    const float* __restrict__ fx, const float* __restrict__ fy,
    const float* __restrict__ W1base,            // [NEXP][FF][EE]
    const float* __restrict__ gbase, const float* __restrict__ bbase,
    const float* __restrict__ W2base, const float* __restrict__ b2base,
    const int* __restrict__ rowlists, const int* __restrict__ cnts,
    float* __restrict__ logits_out,
    int* __restrict__ cnt_next, int* __restrict__ rows_next,
    int* __restrict__ ticks)
{
    constexpr int R    = 4 * RT;
    constexpr int CMAX = BB / R;                 // chunk capacity per expert
    const int tid  = threadIdx.x;
    const int cg   = tid & 63;
    const int rg   = tid >> 6;
    const int slot = blockIdx.x, nslot = gridDim.x;
    const int seg  = blockIdx.y;
    const int e    = blockIdx.z;
    const int f0   = seg * FS;
    const int cnt  = DENSE ? BB : cnts[e];
    const float* __restrict__ W1 =
        W1base + (size_t)e * FF * EE + (size_t)f0 * EE + 4 * cg;
    const float* __restrict__ gg = gbase  + (size_t)e * EE;
    const float* __restrict__ bv = bbase  + (size_t)e * EE;
    const float* __restrict__ W2 = W2base + (size_t)e * EE * L;
    const float* __restrict__ b2 = b2base + (size_t)e * L;

    struct FinSm {
        float act[R][EE];
        float reds[R][8], redq[R][8];
        float mean[R], rstd[R];
        float lg[R][32];
    };
    union Sm {
        float2 feat[R][FS];   // duplicated pairs for LDS.64 multiplicand
        FinSm  fin;
    };
    __shared__ Sm sm;
    __shared__ int sflag;

    for (int c = slot; c * R < cnt; c += nslot) {
        const int start = c * R;
        const int nr = min(R, cnt - start);
        const int* rowids = DENSE ? nullptr : (rowlists + e * BB + start);

        // ---- cooperative feature load (duplicated pairs) ----------------
        #pragma unroll
        for (int i = tid; i < R * FS / 4; i += 256) {
            int r  = i / (FS / 4);
            int j  = (i % (FS / 4)) * 4;
            int rr = (r < nr) ? r : 0;
            int b  = DENSE ? (start + rr) : rowids[rr];
            float4 v = *(const float4*)(fx + (size_t)b * FF + f0 + j);
            if (MIX) {
                float4 u = *(const float4*)(fy + (size_t)b * FF + f0 + j);
                v.x = 0.6f * v.x + 0.4f * u.x;
                v.y = 0.6f * v.y + 0.4f * u.y;
                v.z = 0.6f * v.z + 0.4f * u.z;
                v.w = 0.6f * v.w + 0.4f * u.w;
            }
            sm.feat[r][j + 0] = make_float2(v.x, v.x);
            sm.feat[r][j + 1] = make_float2(v.y, v.y);
            sm.feat[r][j + 2] = make_float2(v.z, v.z);
            sm.feat[r][j + 3] = make_float2(v.w, v.w);
        }
        __syncthreads();

        // ---- register-tile GEMM: RT rows x 4 cols, 8 LDG.128 in flight --
        unsigned long long acc[RT][2];
        #pragma unroll
        for (int t = 0; t < RT; t++) { acc[t][0] = 0ull; acc[t][1] = 0ull; }

        #pragma unroll 8
        for (int f = 0; f < FS; f++) {
            ulonglong2 w = *(const ulonglong2*)(W1 + (size_t)f * EE);
            #pragma unroll
            for (int t = 0; t < RT; t++) {
                unsigned long long fv =
                    *(const unsigned long long*)&sm.feat[rg * RT + t][f];
                fma_f32x2(acc[t][0], fv, w.x);
                fma_f32x2(acc[t][1], fv, w.y);
            }
        }

        // ---- write partials (STG.128) -----------------------------------
        #pragma unroll
        for (int t = 0; t < RT; t++) {
            int r = rg * RT + t;
            if (r < nr) {
                int b = DENSE ? (start + r) : rowids[r];
                float2 lo = unpack2(acc[t][0]);
                float2 hi = unpack2(acc[t][1]);
                *(float4*)&g_part[((size_t)seg * BB + b) * EE + 4 * cg] =
                    make_float4(lo.x, lo.y, hi.x, hi.y);
            }
        }

        // ---- split-K completion ticket ----------------------------------
        __threadfence();
        __syncthreads();
        if (tid == 0) {
            int* tk = &ticks[e * CMAX + c];
            int old = atomicAdd(tk, 1);
            if (old == FSEG - 1) *tk = 0;          // self-reset for replays
            sflag = old;
        }
        __syncthreads();
        if (sflag != FSEG - 1) continue;           // not the last seg-block

        // =================== FINISH (reducer block only) =================
        __threadfence();                           // acquire partials

        float h[R];
        #pragma unroll
        for (int r = 0; r < R; r++) {
            int rr = (r < nr) ? r : 0;
            int b  = DENSE ? (start + rr) : rowids[rr];
            float s = 0.f;
            #pragma unroll
            for (int sg = 0; sg < FSEG; sg++)
                s += g_part[((size_t)sg * BB + b) * EE + tid];
            h[r] = s;
        }

        const int lane = tid & 31, wid = tid >> 5;
        #pragma unroll
        for (int r = 0; r < R; r++) {
            float s = h[r], q = h[r] * h[r];
            #pragma unroll
            for (int o = 16; o; o >>= 1) {
                s += __shfl_xor_sync(0xffffffffu, s, o);
                q += __shfl_xor_sync(0xffffffffu, q, o);
            }
            if (lane == 0) { sm.fin.reds[r][wid] = s; sm.fin.redq[r][wid] = q; }
        }
        __syncthreads();
        if (tid < R) {
            float s = 0.f, q = 0.f;
            #pragma unroll
            for (int w = 0; w < 8; w++) {
                s += sm.fin.reds[tid][w]; q += sm.fin.redq[tid][w];
            }
            float m   = s * (1.0f / EE);
            float var = q * (1.0f / EE) - m * m;
            sm.fin.mean[tid] = m;
            sm.fin.rstd[tid] = rsqrtf(var + 1e-5f);
        }
        __syncthreads();

        const float gt = gg[tid], bt = bv[tid];
        #pragma unroll
        for (int r = 0; r < R; r++) {
            float yv = (h[r] - sm.fin.mean[r]) * sm.fin.rstd[r] * gt + bt;
            sm.fin.act[r][tid] = fmaxf(yv, 0.0f);
        }
        __syncthreads();

        // second matmul: logits
        for (int i = tid; i < nr * L; i += 256) {
            int r = i / L, col = i % L;
            float a = b2[col];
            const float* ar = sm.fin.act[r];
            #pragma unroll 8
            for (int k = 0; k < EE; k++) a += ar[k] * W2[k * L + col];
            sm.fin.lg[r][col] = a;
            int b = DENSE ? (start + r) : rowids[r];
            logits_out[(size_t)b * L + col] = a;
        }
        __syncthreads();

        // argmax + scatter into next-level routing list
        if (cnt_next && tid < nr) {
            float best = sm.fin.lg[tid][0];
            int   bi   = 0;
            #pragma unroll
            for (int col = 1; col < L; col++) {
                float v = sm.fin.lg[tid][col];
                if (v > best) { best = v; bi = col; }
            }
            int b   = DENSE ? (start + tid) : rowids[tid];
            int nxt = e * L + bi;
            int pos = atomicAdd(&cnt_next[nxt], 1);
            rows_next[nxt * BB + pos] = b;
        }
        __syncthreads();   // protect unioned smem before next chunk
    }
}

// ---------------------------------------------------------------------------
extern "C" void kernel_launch(void* const* d_in, const int* in_sizes, int n_in,
                              void* d_out, int out_size)
{
    const float* x    = (const float*)d_in[0];
    const float* y    = (const float*)d_in[1];
    const float* l1W1 = (const float*)d_in[2];
    const float* l1g  = (const float*)d_in[3];
    const float* l1b  = (const float*)d_in[4];
    const float* l1W2 = (const float*)d_in[5];
    const float* l1b2 = (const float*)d_in[6];
    const float* l2W1 = (const float*)d_in[7];
    const float* l2g  = (const float*)d_in[8];
    const float* l2b  = (const float*)d_in[9];
    const float* l2W2 = (const float*)d_in[10];
    const float* l2b2 = (const float*)d_in[11];
    const float* l3W1 = (const float*)d_in[12];
    const float* l3g  = (const float*)d_in[13];
    const float* l3b  = (const float*)d_in[14];
    const float* l3W2 = (const float*)d_in[15];
    const float* l3b2 = (const float*)d_in[16];
    float* out = (float*)d_out;

    int *rows2, *cnt2, *rows3, *cnt3, *t1, *t2, *t3;
    cudaGetSymbolAddress((void**)&rows2, g_rows2);
    cudaGetSymbolAddress((void**)&cnt2,  g_cnt2);
    cudaGetSymbolAddress((void**)&rows3, g_rows3);
    cudaGetSymbolAddress((void**)&cnt3,  g_cnt3);
    cudaGetSymbolAddress((void**)&t1,    g_tick1);
    cudaGetSymbolAddress((void**)&t2,    g_tick2);
    cudaGetSymbolAddress((void**)&t3,    g_tick3);

    k_init<<<1, 256>>>();

    // level 1: dense, RT=4 (R=16), 64 chunks, one chunk per slot-block
    k_level<4, L1C, false, true><<<dim3(64, FSEG, 1), 256>>>(
        x, nullptr, l1W1, l1g, l1b, l1W2, l1b2,
        nullptr, nullptr, out, cnt2, rows2, t1);

    // level 2: 16 experts, mixed features, RT=4 (R=16)
    k_level<4, L2C, true, false><<<dim3(8, FSEG, L1C), 256>>>(
        x, y, l2W1, l2g, l2b, l2W2, l2b2,
        rows2, cnt2, out + (size_t)BB * L1C, cnt3, rows3, t2);

    // level 3: 128 experts, RT=2 (R=8)
    k_level<2, L3C, false, false><<<dim3(2, FSEG, NE3), 256>>>(
        x, nullptr, l3W1, l3g, l3b, l3W2, l3b2,
        rows3, cnt3, out + (size_t)BB * (L1C + L2C), nullptr, nullptr, t3);
}

// round 9
// speedup vs baseline: 1.3635x; 1.3635x over previous
#include <cuda_runtime.h>

// ---------------------------------------------------------------------------
// MultiLevelClassifier — routed experts, round 6.
//
// R5 post-mortem: fused l3 kernel = 249us moving 128MB at 424GB/s, pure
// DRAM-latency bound. regs=40 meant ptxas couldn't keep 8 LDG.128 in
// flight (needs 32 regs just for data) -> MLP_eff ~2.
//
// R6: ONLY change = inner GEMM loop is explicitly software-staged:
//   per stage, 8 independent LDG.128 weight loads land in a register
//   array (fully unrolled), then the FMAs run. __launch_bounds__(256,2)
//   raises the reg cap so the staging survives. MLP=8/thread guaranteed
//   -> ~65KB/SM outstanding vs ~11KB needed to saturate HBM.
// Fused finish (split-K last-block-reduces with self-resetting tickets)
// unchanged from the passing R5 kernel.
// ---------------------------------------------------------------------------

#define BB   1024
#define FF   1024
#define EE   256
#define L1C  16
#define L2C  8
#define L3C  32
#define NE3  128
#define FSEG 8
#define FS   (FF / FSEG)   // 128
#define STG  8             // f's staged per load batch (8 x LDG.128)

// scratch (device globals — no allocation allowed; zero-initialized)
__device__ int   g_cnt2[L1C];
__device__ int   g_cnt3[NE3];
__device__ int   g_rows2[L1C * BB];
__device__ int   g_rows3[NE3 * BB];
__device__ float g_part[FSEG * BB * EE];   // 8 MB split-K partials
__device__ int   g_tick1[64];
__device__ int   g_tick2[L1C * 64];
__device__ int   g_tick3[NE3 * 128];

// ---- packed f32x2 helpers --------------------------------------------------
__device__ __forceinline__ void fma_f32x2(unsigned long long& d,
                                          unsigned long long a,
                                          unsigned long long b) {
    asm("fma.rn.f32x2 %0, %1, %2, %0;" : "+l"(d) : "l"(a), "l"(b));
}
__device__ __forceinline__ float2 unpack2(unsigned long long v) {
    float2 r;
    asm("mov.b64 {%0, %1}, %2;" : "=f"(r.x), "=f"(r.y) : "l"(v));
    return r;
}

// ---------------------------------------------------------------------------
__global__ void k_init() {
    int t = threadIdx.x;
    if (t < L1C) g_cnt2[t] = 0;
    if (t < NE3) g_cnt3[t] = 0;
}

// ---------------------------------------------------------------------------
// Fused level kernel. Block (slot, seg, expert), 256 threads.
// GEMM: cg = tid&63 -> cols 4cg..4cg+3, rg = tid>>6 -> rows rg*RT..
// Weight loads staged 8-deep in registers. Finish in last seg-block.
// ---------------------------------------------------------------------------
template <int RT, int L, bool MIX, bool DENSE>
__global__ __launch_bounds__(256, 2) void k_level(
    const float* __restrict__ fx, const float* __restrict__ fy,
    const float* __restrict__ W1base,            // [NEXP][FF][EE]
    const float* __restrict__ gbase, const float* __restrict__ bbase,
    const float* __restrict__ W2base, const float* __restrict__ b2base,
    const int* __restrict__ rowlists, const int* __restrict__ cnts,
    float* __restrict__ logits_out,
    int* __restrict__ cnt_next, int* __restrict__ rows_next,
    int* __restrict__ ticks)
{
    constexpr int R    = 4 * RT;
    constexpr int CMAX = BB / R;
    const int tid  = threadIdx.x;
    const int cg   = tid & 63;
    const int rg   = tid >> 6;
    const int slot = blockIdx.x, nslot = gridDim.x;
    const int seg  = blockIdx.y;
    const int e    = blockIdx.z;
    const int f0   = seg * FS;
    const int cnt  = DENSE ? BB : cnts[e];
    const float* __restrict__ W1 =
        W1base + (size_t)e * FF * EE + (size_t)f0 * EE + 4 * cg;
    const float* __restrict__ gg = gbase  + (size_t)e * EE;
    const float* __restrict__ bv = bbase  + (size_t)e * EE;
    const float* __restrict__ W2 = W2base + (size_t)e * EE * L;
    const float* __restrict__ b2 = b2base + (size_t)e * L;

    struct FinSm {
        float act[R][EE];
        float reds[R][8], redq[R][8];
        float mean[R], rstd[R];
        float lg[R][32];
    };
    union Sm {
        float2 feat[R][FS];   // duplicated pairs for LDS.64 multiplicand
        FinSm  fin;
    };
    __shared__ Sm sm;
    __shared__ int sflag;

    for (int c = slot; c * R < cnt; c += nslot) {
        const int start = c * R;
        const int nr = min(R, cnt - start);
        const int* rowids = DENSE ? nullptr : (rowlists + e * BB + start);

        // ---- cooperative feature load (duplicated pairs) ----------------
        #pragma unroll
        for (int i = tid; i < R * FS / 4; i += 256) {
            int r  = i / (FS / 4);
            int j  = (i % (FS / 4)) * 4;
            int rr = (r < nr) ? r : 0;
            int b  = DENSE ? (start + rr) : rowids[rr];
            float4 v = *(const float4*)(fx + (size_t)b * FF + f0 + j);
            if (MIX) {
                float4 u = *(const float4*)(fy + (size_t)b * FF + f0 + j);
                v.x = 0.6f * v.x + 0.4f * u.x;
                v.y = 0.6f * v.y + 0.4f * u.y;
                v.z = 0.6f * v.z + 0.4f * u.z;
                v.w = 0.6f * v.w + 0.4f * u.w;
            }
            sm.feat[r][j + 0] = make_float2(v.x, v.x);
            sm.feat[r][j + 1] = make_float2(v.y, v.y);
            sm.feat[r][j + 2] = make_float2(v.z, v.z);
            sm.feat[r][j + 3] = make_float2(v.w, v.w);
        }
        __syncthreads();

        // ---- staged register-tile GEMM ----------------------------------
        unsigned long long acc[RT][2];
        #pragma unroll
        for (int t = 0; t < RT; t++) { acc[t][0] = 0ull; acc[t][1] = 0ull; }

        for (int fb = 0; fb < FS; fb += STG) {
            // phase 1: 8 independent LDG.128 into registers (MLP=8)
            ulonglong2 w[STG];
            #pragma unroll
            for (int i = 0; i < STG; i++)
                w[i] = *(const ulonglong2*)(W1 + (size_t)(fb + i) * EE);
            // phase 2: consume
            #pragma unroll
            for (int i = 0; i < STG; i++) {
                #pragma unroll
                for (int t = 0; t < RT; t++) {
                    unsigned long long fv =
                        *(const unsigned long long*)&sm.feat[rg * RT + t][fb + i];
                    fma_f32x2(acc[t][0], fv, w[i].x);
                    fma_f32x2(acc[t][1], fv, w[i].y);
                }
            }
        }

        // ---- write partials (STG.128) -----------------------------------
        #pragma unroll
        for (int t = 0; t < RT; t++) {
            int r = rg * RT + t;
            if (r < nr) {
                int b = DENSE ? (start + r) : rowids[r];
                float2 lo = unpack2(acc[t][0]);
                float2 hi = unpack2(acc[t][1]);
                *(float4*)&g_part[((size_t)seg * BB + b) * EE + 4 * cg] =
                    make_float4(lo.x, lo.y, hi.x, hi.y);
            }
        }

        // ---- split-K completion ticket ----------------------------------
        __threadfence();
        __syncthreads();
        if (tid == 0) {
            int* tk = &ticks[e * CMAX + c];
            int old = atomicAdd(tk, 1);
            if (old == FSEG - 1) *tk = 0;          // self-reset for replays
            sflag = old;
        }
        __syncthreads();
        if (sflag != FSEG - 1) continue;

        // =================== FINISH (reducer block only) =================
        __threadfence();

        float h[R];
        #pragma unroll
        for (int r = 0; r < R; r++) {
            int rr = (r < nr) ? r : 0;
            int b  = DENSE ? (start + rr) : rowids[rr];
            float s = 0.f;
            #pragma unroll
            for (int sg = 0; sg < FSEG; sg++)
                s += g_part[((size_t)sg * BB + b) * EE + tid];
            h[r] = s;
        }

        const int lane = tid & 31, wid = tid >> 5;
        #pragma unroll
        for (int r = 0; r < R; r++) {
            float s = h[r], q = h[r] * h[r];
            #pragma unroll
            for (int o = 16; o; o >>= 1) {
                s += __shfl_xor_sync(0xffffffffu, s, o);
                q += __shfl_xor_sync(0xffffffffu, q, o);
            }
            if (lane == 0) { sm.fin.reds[r][wid] = s; sm.fin.redq[r][wid] = q; }
        }
        __syncthreads();
        if (tid < R) {
            float s = 0.f, q = 0.f;
            #pragma unroll
            for (int w2i = 0; w2i < 8; w2i++) {
                s += sm.fin.reds[tid][w2i]; q += sm.fin.redq[tid][w2i];
            }
            float m   = s * (1.0f / EE);
            float var = q * (1.0f / EE) - m * m;
            sm.fin.mean[tid] = m;
            sm.fin.rstd[tid] = rsqrtf(var + 1e-5f);
        }
        __syncthreads();

        const float gt = gg[tid], bt = bv[tid];
        #pragma unroll
        for (int r = 0; r < R; r++) {
            float yv = (h[r] - sm.fin.mean[r]) * sm.fin.rstd[r] * gt + bt;
            sm.fin.act[r][tid] = fmaxf(yv, 0.0f);
        }
        __syncthreads();

        // second matmul: logits
        for (int i = tid; i < nr * L; i += 256) {
            int r = i / L, col = i % L;
            float a = b2[col];
            const float* ar = sm.fin.act[r];
            #pragma unroll 8
            for (int k = 0; k < EE; k++) a += ar[k] * W2[k * L + col];
            sm.fin.lg[r][col] = a;
            int b = DENSE ? (start + r) : rowids[r];
            logits_out[(size_t)b * L + col] = a;
        }
        __syncthreads();

        // argmax + scatter
        if (cnt_next && tid < nr) {
            float best = sm.fin.lg[tid][0];
            int   bi   = 0;
            #pragma unroll
            for (int col = 1; col < L; col++) {
                float v = sm.fin.lg[tid][col];
                if (v > best) { best = v; bi = col; }
            }
            int b   = DENSE ? (start + tid) : rowids[tid];
            int nxt = e * L + bi;
            int pos = atomicAdd(&cnt_next[nxt], 1);
            rows_next[nxt * BB + pos] = b;
        }
        __syncthreads();
    }
}

// ---------------------------------------------------------------------------
extern "C" void kernel_launch(void* const* d_in, const int* in_sizes, int n_in,
                              void* d_out, int out_size)
{
    const float* x    = (const float*)d_in[0];
    const float* y    = (const float*)d_in[1];
    const float* l1W1 = (const float*)d_in[2];
    const float* l1g  = (const float*)d_in[3];
    const float* l1b  = (const float*)d_in[4];
    const float* l1W2 = (const float*)d_in[5];
    const float* l1b2 = (const float*)d_in[6];
    const float* l2W1 = (const float*)d_in[7];
    const float* l2g  = (const float*)d_in[8];
    const float* l2b  = (const float*)d_in[9];
    const float* l2W2 = (const float*)d_in[10];
    const float* l2b2 = (const float*)d_in[11];
    const float* l3W1 = (const float*)d_in[12];
    const float* l3g  = (const float*)d_in[13];
    const float* l3b  = (const float*)d_in[14];
    const float* l3W2 = (const float*)d_in[15];
    const float* l3b2 = (const float*)d_in[16];
    float* out = (float*)d_out;

    int *rows2, *cnt2, *rows3, *cnt3, *t1, *t2, *t3;
    cudaGetSymbolAddress((void**)&rows2, g_rows2);
    cudaGetSymbolAddress((void**)&cnt2,  g_cnt2);
    cudaGetSymbolAddress((void**)&rows3, g_rows3);
    cudaGetSymbolAddress((void**)&cnt3,  g_cnt3);
    cudaGetSymbolAddress((void**)&t1,    g_tick1);
    cudaGetSymbolAddress((void**)&t2,    g_tick2);
    cudaGetSymbolAddress((void**)&t3,    g_tick3);

    k_init<<<1, 256>>>();

    // level 1: dense, RT=4 (R=16), 64 chunks
    k_level<4, L1C, false, true><<<dim3(64, FSEG, 1), 256>>>(
        x, nullptr, l1W1, l1g, l1b, l1W2, l1b2,
        nullptr, nullptr, out, cnt2, rows2, t1);

    // level 2: 16 experts, mixed features, RT=4 (R=16)
    k_level<4, L2C, true, false><<<dim3(8, FSEG, L1C), 256>>>(
        x, y, l2W1, l2g, l2b, l2W2, l2b2,
        rows2, cnt2, out + (size_t)BB * L1C, cnt3, rows3, t2);

    // level 3: 128 experts, RT=2 (R=8)
    k_level<2, L3C, false, false><<<dim3(2, FSEG, NE3), 256>>>(
        x, nullptr, l3W1, l3g, l3b, l3W2, l3b2,
        rows3, cnt3, out + (size_t)BB * (L1C + L2C), nullptr, nullptr, t3);
}

// round 11
// speedup vs baseline: 1.6031x; 1.1757x over previous
#include <cuda_runtime.h>

// ---------------------------------------------------------------------------
// MultiLevelClassifier — routed experts, round 7.
//
// R6 post-mortem: per-thread LDG staging = registers buy MLP but destroy
// occupancy (114 regs, 2 blocks/SM, 545 GB/s). Also 4x duplicated weight
// requests across rg subgroups.
//
// R7: cp.async (LDGSTS) weight pipeline into smem. Fire-and-forget copies
// keep a 16KB stage in flight per block with ZERO register cost; compute
// reads weights from smem (dup traffic hits the smem crossbar, not L2).
// regs ~45, smem ~41KB -> ~5 blocks/SM, 80KB/SM DRAM bytes in flight.
// Fused split-K finish (last-block-reduces, self-resetting tickets)
// unchanged from the passing R5/R6 kernels.
// ---------------------------------------------------------------------------

#define BB   1024
#define FF   1024
#define EE   256
#define L1C  16
#define L2C  8
#define L3C  32
#define NE3  128
#define FSEG 8
#define FS   (FF / FSEG)     // 128 features per seg-block
#define SROWS 16             // f-rows per cp.async stage (16 KB)
#define NST  (FS / SROWS)    // 8 stages per chunk

// scratch (device globals — no allocation allowed; zero-initialized)
__device__ int   g_cnt2[L1C];
__device__ int   g_cnt3[NE3];
__device__ int   g_rows2[L1C * BB];
__device__ int   g_rows3[NE3 * BB];
__device__ float g_part[FSEG * BB * EE];   // 8 MB split-K partials
__device__ int   g_tick1[64];
__device__ int   g_tick2[L1C * 64];
__device__ int   g_tick3[NE3 * 128];

// ---- packed f32x2 helpers --------------------------------------------------
__device__ __forceinline__ unsigned long long pack2f(float a, float b) {
    unsigned long long r;
    asm("mov.b64 %0, {%1, %2};" : "=l"(r) : "f"(a), "f"(b));
    return r;
}
__device__ __forceinline__ void fma_f32x2(unsigned long long& d,
                                          unsigned long long a,
                                          unsigned long long b) {
    asm("fma.rn.f32x2 %0, %1, %2, %0;" : "+l"(d) : "l"(a), "l"(b));
}
__device__ __forceinline__ float2 unpack2(unsigned long long v) {
    float2 r;
    asm("mov.b64 {%0, %1}, %2;" : "=f"(r.x), "=f"(r.y) : "l"(v));
    return r;
}

// ---- cp.async helpers ------------------------------------------------------
__device__ __forceinline__ void cp_async16(void* sdst, const void* gsrc) {
    unsigned sa = (unsigned)__cvta_generic_to_shared(sdst);
    asm volatile("cp.async.cg.shared.global [%0], [%1], 16;\n"
                 :: "r"(sa), "l"(gsrc));
}
__device__ __forceinline__ void cp_commit() {
    asm volatile("cp.async.commit_group;\n");
}
template <int N>
__device__ __forceinline__ void cp_wait() {
    asm volatile("cp.async.wait_group %0;\n" :: "n"(N));
}

// ---------------------------------------------------------------------------
__global__ void k_init() {
    int t = threadIdx.x;
    if (t < L1C) g_cnt2[t] = 0;
    if (t < NE3) g_cnt3[t] = 0;
}

// ---------------------------------------------------------------------------
// Fused level kernel. Block (slot, seg, expert), 256 threads.
//   cg = tid&63 -> cols 4cg..4cg+3 ; rg = tid>>6 -> rows rg*RT.. (R=4*RT)
// Weights pipelined global->smem via cp.async, double-buffered 16KB stages.
// Finish (split-K reduce, LN, ReLU, W2, argmax, scatter) in last seg-block.
// ---------------------------------------------------------------------------
template <int RT, int L, bool MIX, bool DENSE>
__global__ __launch_bounds__(256) void k_level(
    const float* __restrict__ fx, const float* __restrict__ fy,
    const float* __restrict__ W1base,            // [NEXP][FF][EE]
    const float* __restrict__ gbase, const float* __restrict__ bbase,
    const float* __restrict__ W2base, const float* __restrict__ b2base,
    const int* __restrict__ rowlists, const int* __restrict__ cnts,
    float* __restrict__ logits_out,
    int* __restrict__ cnt_next, int* __restrict__ rows_next,
    int* __restrict__ ticks)
{
    constexpr int R    = 4 * RT;
    constexpr int CMAX = BB / R;
    const int tid  = threadIdx.x;
    const int cg   = tid & 63;
    const int rg   = tid >> 6;
    const int slot = blockIdx.x, nslot = gridDim.x;
    const int seg  = blockIdx.y;
    const int e    = blockIdx.z;
    const int f0   = seg * FS;
    const int cnt  = DENSE ? BB : cnts[e];
    // contiguous 128 KB weight slice for this (expert, seg)
    const float* __restrict__ Wseg =
        W1base + (size_t)e * FF * EE + (size_t)f0 * EE;
    const float* __restrict__ gg = gbase  + (size_t)e * EE;
    const float* __restrict__ bv = bbase  + (size_t)e * EE;
    const float* __restrict__ W2 = W2base + (size_t)e * EE * L;
    const float* __restrict__ b2 = b2base + (size_t)e * L;

    struct FinSm {
        float act[R][EE];
        float reds[R][8], redq[R][8];
        float mean[R], rstd[R];
        float lg[R][32];
    };
    union U {
        float wbuf[2][SROWS * EE];   // 2 x 16 KB weight stages
        FinSm fin;                   // finish scratch (<= 20 KB)
    };
    __shared__ U sm;
    __shared__ float feat[R][FS];    // plain features (broadcast reads)
    __shared__ int sflag;

    for (int c = slot; c * R < cnt; c += nslot) {
        const int start = c * R;
        const int nr = min(R, cnt - start);
        const int* rowids = DENSE ? nullptr : (rowlists + e * BB + start);

        // ---- kick off weight stage 0, then gather features --------------
        {
            const float* gs = Wseg;                     // stage 0
            #pragma unroll
            for (int k = 0; k < 4; k++)
                cp_async16(&sm.wbuf[0][(k * 256 + tid) * 4],
                           gs + (k * 256 + tid) * 4);
            cp_commit();
        }
        #pragma unroll
        for (int i = tid; i < R * FS / 4; i += 256) {
            int r  = i / (FS / 4);
            int j  = (i % (FS / 4)) * 4;
            int rr = (r < nr) ? r : 0;
            int b  = DENSE ? (start + rr) : rowids[rr];
            float4 v = *(const float4*)(fx + (size_t)b * FF + f0 + j);
            if (MIX) {
                float4 u = *(const float4*)(fy + (size_t)b * FF + f0 + j);
                v.x = 0.6f * v.x + 0.4f * u.x;
                v.y = 0.6f * v.y + 0.4f * u.y;
                v.z = 0.6f * v.z + 0.4f * u.z;
                v.w = 0.6f * v.w + 0.4f * u.w;
            }
            *(float4*)&feat[r][j] = v;
        }

        // ---- pipelined GEMM over NST stages ------------------------------
        unsigned long long acc[RT][2];
        #pragma unroll
        for (int t = 0; t < RT; t++) { acc[t][0] = 0ull; acc[t][1] = 0ull; }

        #pragma unroll
        for (int s = 0; s < NST; s++) {
            if (s + 1 < NST) {
                const float* gs = Wseg + (size_t)(s + 1) * SROWS * EE;
                float* sd = sm.wbuf[(s + 1) & 1];
                #pragma unroll
                for (int k = 0; k < 4; k++)
                    cp_async16(&sd[(k * 256 + tid) * 4],
                               gs + (k * 256 + tid) * 4);
                cp_commit();
                cp_wait<1>();                 // stage s complete
            } else {
                cp_wait<0>();
            }
            __syncthreads();                  // all threads' copies visible

            const float* wb = sm.wbuf[s & 1];
            const int fb = s * SROWS;
            #pragma unroll
            for (int f = 0; f < SROWS; f++) {
                ulonglong2 w = *(const ulonglong2*)&wb[f * EE + 4 * cg];
                #pragma unroll
                for (int t = 0; t < RT; t++) {
                    float v = feat[rg * RT + t][fb + f];
                    unsigned long long fv = pack2f(v, v);
                    fma_f32x2(acc[t][0], fv, w.x);
                    fma_f32x2(acc[t][1], fv, w.y);
                }
            }
            __syncthreads();                  // buffer free for reuse
        }

        // ---- write partials (STG.128) -----------------------------------
        #pragma unroll
        for (int t = 0; t < RT; t++) {
            int r = rg * RT + t;
            if (r < nr) {
                int b = DENSE ? (start + r) : rowids[r];
                float2 lo = unpack2(acc[t][0]);
                float2 hi = unpack2(acc[t][1]);
                *(float4*)&g_part[((size_t)seg * BB + b) * EE + 4 * cg] =
                    make_float4(lo.x, lo.y, hi.x, hi.y);
            }
        }

        // ---- split-K completion ticket ----------------------------------
        __threadfence();
        __syncthreads();
        if (tid == 0) {
            int* tk = &ticks[e * CMAX + c];
            int old = atomicAdd(tk, 1);
            if (old == FSEG - 1) *tk = 0;          // self-reset for replays
            sflag = old;
        }
        __syncthreads();
        if (sflag != FSEG - 1) continue;

        // =================== FINISH (reducer block only) =================
        __threadfence();

        float h[R];
        #pragma unroll
        for (int r = 0; r < R; r++) {
            int rr = (r < nr) ? r : 0;
            int b  = DENSE ? (start + rr) : rowids[rr];
            float s = 0.f;
            #pragma unroll
            for (int sg = 0; sg < FSEG; sg++)
                s += g_part[((size_t)sg * BB + b) * EE + tid];
            h[r] = s;
        }

        const int lane = tid & 31, wid = tid >> 5;
        #pragma unroll
        for (int r = 0; r < R; r++) {
            float s = h[r], q = h[r] * h[r];
            #pragma unroll
            for (int o = 16; o; o >>= 1) {
                s += __shfl_xor_sync(0xffffffffu, s, o);
                q += __shfl_xor_sync(0xffffffffu, q, o);
            }
            if (lane == 0) { sm.fin.reds[r][wid] = s; sm.fin.redq[r][wid] = q; }
        }
        __syncthreads();
        if (tid < R) {
            float s = 0.f, q = 0.f;
            #pragma unroll
            for (int w2i = 0; w2i < 8; w2i++) {
                s += sm.fin.reds[tid][w2i]; q += sm.fin.redq[tid][w2i];
            }
            float m   = s * (1.0f / EE);
            float var = q * (1.0f / EE) - m * m;
            sm.fin.mean[tid] = m;
            sm.fin.rstd[tid] = rsqrtf(var + 1e-5f);
        }
        __syncthreads();

        const float gt = gg[tid], bt = bv[tid];
        #pragma unroll
        for (int r = 0; r < R; r++) {
            float yv = (h[r] - sm.fin.mean[r]) * sm.fin.rstd[r] * gt + bt;
            sm.fin.act[r][tid] = fmaxf(yv, 0.0f);
        }
        __syncthreads();

        // second matmul: logits
        for (int i = tid; i < nr * L; i += 256) {
            int r = i / L, col = i % L;
            float a = b2[col];
            const float* ar = sm.fin.act[r];
            #pragma unroll 8
            for (int k = 0; k < EE; k++) a += ar[k] * W2[k * L + col];
            sm.fin.lg[r][col] = a;
            int b = DENSE ? (start + r) : rowids[r];
            logits_out[(size_t)b * L + col] = a;
        }
        __syncthreads();

        // argmax + scatter
        if (cnt_next && tid < nr) {
            float best = sm.fin.lg[tid][0];
            int   bi   = 0;
            #pragma unroll
            for (int col = 1; col < L; col++) {
                float v = sm.fin.lg[tid][col];
                if (v > best) { best = v; bi = col; }
            }
            int b   = DENSE ? (start + tid) : rowids[tid];
            int nxt = e * L + bi;
            int pos = atomicAdd(&cnt_next[nxt], 1);
            rows_next[nxt * BB + pos] = b;
        }
        __syncthreads();   // protect unioned smem before next chunk
    }
}

// ---------------------------------------------------------------------------
extern "C" void kernel_launch(void* const* d_in, const int* in_sizes, int n_in,
                              void* d_out, int out_size)
{
    const float* x    = (const float*)d_in[0];
    const float* y    = (const float*)d_in[1];
    const float* l1W1 = (const float*)d_in[2];
    const float* l1g  = (const float*)d_in[3];
    const float* l1b  = (const float*)d_in[4];
    const float* l1W2 = (const float*)d_in[5];
    const float* l1b2 = (const float*)d_in[6];
    const float* l2W1 = (const float*)d_in[7];
    const float* l2g  = (const float*)d_in[8];
    const float* l2b  = (const float*)d_in[9];
    const float* l2W2 = (const float*)d_in[10];
    const float* l2b2 = (const float*)d_in[11];
    const float* l3W1 = (const float*)d_in[12];
    const float* l3g  = (const float*)d_in[13];
    const float* l3b  = (const float*)d_in[14];
    const float* l3W2 = (const float*)d_in[15];
    const float* l3b2 = (const float*)d_in[16];
    float* out = (float*)d_out;

    int *rows2, *cnt2, *rows3, *cnt3, *t1, *t2, *t3;
    cudaGetSymbolAddress((void**)&rows2, g_rows2);
    cudaGetSymbolAddress((void**)&cnt2,  g_cnt2);
    cudaGetSymbolAddress((void**)&rows3, g_rows3);
    cudaGetSymbolAddress((void**)&cnt3,  g_cnt3);
    cudaGetSymbolAddress((void**)&t1,    g_tick1);
    cudaGetSymbolAddress((void**)&t2,    g_tick2);
    cudaGetSymbolAddress((void**)&t3,    g_tick3);

    k_init<<<1, 256>>>();

    // level 1: dense, RT=4 (R=16), 64 chunks
    k_level<4, L1C, false, true><<<dim3(64, FSEG, 1), 256>>>(
        x, nullptr, l1W1, l1g, l1b, l1W2, l1b2,
        nullptr, nullptr, out, cnt2, rows2, t1);

    // level 2: 16 experts, mixed features, RT=4 (R=16)
    k_level<4, L2C, true, false><<<dim3(8, FSEG, L1C), 256>>>(
        x, y, l2W1, l2g, l2b, l2W2, l2b2,
        rows2, cnt2, out + (size_t)BB * L1C, cnt3, rows3, t2);

    // level 3: 128 experts, RT=2 (R=8)
    k_level<2, L3C, false, false><<<dim3(2, FSEG, NE3), 256>>>(
        x, nullptr, l3W1, l3g, l3b, l3W2, l3b2,
        rows3, cnt3, out + (size_t)BB * (L1C + L2C), nullptr, nullptr, t3);
}